// round 1
// baseline (speedup 1.0000x reference)
#include <cuda_runtime.h>

#define C        128
#define KNBR     27
#define TM       128
#define KC       32
#define NTHREADS 256
#define NMAX     300000

// scratch (alloc-free rule: __device__ globals)
__device__ float g_bufA[(size_t)NMAX * C];
__device__ float g_bufB[(size_t)NMAX * C];

static __device__ __forceinline__ unsigned long long pack2(float x, float y) {
    unsigned long long r;
    asm("mov.b64 %0, {%1, %2};" : "=l"(r) : "r"(__float_as_uint(x)), "r"(__float_as_uint(y)));
    return r;
}
static __device__ __forceinline__ void unpack2(unsigned long long v, float& x, float& y) {
    unsigned lo, hi;
    asm("mov.b64 {%0, %1}, %2;" : "=r"(lo), "=r"(hi) : "l"(v));
    x = __uint_as_float(lo);
    y = __uint_as_float(hi);
}
#define FMA2(d, a, b) asm("fma.rn.f32x2 %0, %1, %2, %0;" : "+l"(d) : "l"(a), "l"(b))

// ---------------------------------------------------------------------------
// Generic sparse-conv / GEMM tile kernel.
//   out[row] = epilogue( sum_k gather_k(in)[row] @ W[k] )
// nbr == nullptr  -> identity gather (dense GEMM), used for the MLP layers.
// resid != nullptr -> add resid[row] before relu decision.
// ---------------------------------------------------------------------------
__global__ __launch_bounds__(NTHREADS, 2)
void sconv_kernel(const float* __restrict__ in, float* __restrict__ out,
                  const float* __restrict__ W, const float* __restrict__ bias,
                  const int* __restrict__ nbr, int Kn,
                  const float* __restrict__ resid, int relu, int n)
{
    __shared__ float As[TM][KC + 1];   // gathered input chunk, row-major, +1 pad
    __shared__ float Bs[KC][C];        // weight chunk
    __shared__ int   s_idx[TM];

    const int tid  = threadIdx.x;
    const int tx   = tid & 15;         // 16 col-groups of 8
    const int ty   = tid >> 4;         // 16 row-groups of 8
    const int row0 = blockIdx.x * TM;

    unsigned long long acc[8][4];
#pragma unroll
    for (int r = 0; r < 8; r++)
#pragma unroll
        for (int c = 0; c < 4; c++) acc[r][c] = 0ULL;

    for (int k = 0; k < Kn; k++) {
        __syncthreads();   // protect s_idx reuse across k
        if (tid < TM) {
            int row = row0 + tid;
            int idx;
            if (row >= n)      idx = -1;
            else if (nbr)      idx = nbr[(long long)row * Kn + k];
            else               idx = row;
            s_idx[tid] = idx;
        }
        __syncthreads();

        const float* Wk = W + (size_t)k * C * C;

        for (int cc = 0; cc < C / KC; cc++) {
            // ---- load gathered A chunk: 128 rows x 32 ci ----
#pragma unroll
            for (int i = 0; i < (TM * KC) / (NTHREADS * 4); i++) {
                int flat = tid + NTHREADS * i;
                int r = flat >> 3;
                int q = flat & 7;
                int idx = s_idx[r];
                float4 v = make_float4(0.f, 0.f, 0.f, 0.f);
                if (idx >= 0)
                    v = *reinterpret_cast<const float4*>(in + (size_t)idx * C + cc * KC + q * 4);
                As[r][q * 4 + 0] = v.x;
                As[r][q * 4 + 1] = v.y;
                As[r][q * 4 + 2] = v.z;
                As[r][q * 4 + 3] = v.w;
            }
            // ---- load W chunk: 32 ci x 128 co ----
#pragma unroll
            for (int i = 0; i < (KC * C) / (NTHREADS * 4); i++) {
                int flat = tid + NTHREADS * i;
                int ci = flat >> 5;
                int q  = flat & 31;
                float4 v = *reinterpret_cast<const float4*>(Wk + (size_t)(cc * KC + ci) * C + q * 4);
                *reinterpret_cast<float4*>(&Bs[ci][q * 4]) = v;
            }
            __syncthreads();

            // ---- 8x8 register tile, packed f32x2 FMA ----
#pragma unroll
            for (int ci = 0; ci < KC; ci++) {
                float4 b0 = *reinterpret_cast<const float4*>(&Bs[ci][tx * 8]);
                float4 b1 = *reinterpret_cast<const float4*>(&Bs[ci][tx * 8 + 4]);
                unsigned long long bb0 = pack2(b0.x, b0.y);
                unsigned long long bb1 = pack2(b0.z, b0.w);
                unsigned long long bb2 = pack2(b1.x, b1.y);
                unsigned long long bb3 = pack2(b1.z, b1.w);
#pragma unroll
                for (int r = 0; r < 8; r++) {
                    float av = As[ty * 8 + r][ci];
                    unsigned long long a2 = pack2(av, av);
                    FMA2(acc[r][0], a2, bb0);
                    FMA2(acc[r][1], a2, bb1);
                    FMA2(acc[r][2], a2, bb2);
                    FMA2(acc[r][3], a2, bb3);
                }
            }
            __syncthreads();
        }
    }

    // ---- epilogue: bias (+resid) (+relu), vectorized store ----
    float bv[8];
#pragma unroll
    for (int j = 0; j < 8; j++) bv[j] = bias[tx * 8 + j];

#pragma unroll
    for (int r = 0; r < 8; r++) {
        int row = row0 + ty * 8 + r;
        if (row >= n) break;
        float v[8];
#pragma unroll
        for (int c = 0; c < 4; c++) unpack2(acc[r][c], v[c * 2], v[c * 2 + 1]);
#pragma unroll
        for (int j = 0; j < 8; j++) v[j] += bv[j];
        if (resid) {
            const float4* rp = reinterpret_cast<const float4*>(resid + (size_t)row * C + tx * 8);
            float4 r0 = rp[0], r1 = rp[1];
            v[0] += r0.x; v[1] += r0.y; v[2] += r0.z; v[3] += r0.w;
            v[4] += r1.x; v[5] += r1.y; v[6] += r1.z; v[7] += r1.w;
        }
        if (relu) {
#pragma unroll
            for (int j = 0; j < 8; j++) v[j] = fmaxf(v[j], 0.f);
        }
        float4* op = reinterpret_cast<float4*>(out + (size_t)row * C + tx * 8);
        op[0] = make_float4(v[0], v[1], v[2], v[3]);
        op[1] = make_float4(v[4], v[5], v[6], v[7]);
    }
}

// ---------------------------------------------------------------------------
// Input layer: Cin = 1. h[n][c] = relu(b[c] + sum_k mask * x[nbr[n,k]] * Win[k][c])
// ---------------------------------------------------------------------------
__global__ __launch_bounds__(256)
void layer_in_kernel(const float* __restrict__ x, float* __restrict__ out,
                     const float* __restrict__ Win, const float* __restrict__ bin,
                     const int* __restrict__ nbr, int n)
{
    __shared__ float xs[TM][KNBR + 1];
    __shared__ float ws[KNBR][C];
    const int tid  = threadIdx.x;
    const int row0 = blockIdx.x * TM;

    for (int flat = tid; flat < TM * KNBR; flat += 256) {
        int r = flat / KNBR, k = flat % KNBR;
        int row = row0 + r;
        float v = 0.f;
        if (row < n) {
            int idx = nbr[(long long)row * KNBR + k];
            if (idx >= 0) v = x[idx];
        }
        xs[r][k] = v;
    }
    for (int flat = tid; flat < KNBR * C; flat += 256)
        ws[flat / C][flat % C] = Win[flat];
    __syncthreads();

    const int c  = tid & (C - 1);
    const int rg = tid >> 7;     // 0 or 1
    const float b = bin[c];
    for (int r = rg; r < TM; r += 2) {
        int row = row0 + r;
        if (row >= n) continue;
        float acc = b;
#pragma unroll
        for (int k = 0; k < KNBR; k++) acc += xs[r][k] * ws[k][c];
        out[(size_t)row * C + c] = fmaxf(acc, 0.f);
    }
}

// ---------------------------------------------------------------------------
// Final layer: out[n][0:3] = h[n] @ Wf3 + bf3
// ---------------------------------------------------------------------------
__global__ __launch_bounds__(256)
void final_kernel(const float* __restrict__ in, float* __restrict__ out,
                  const float* __restrict__ Wf3, const float* __restrict__ bf3, int n)
{
    __shared__ float hs[64][C + 1];
    __shared__ float wl[C * 3];
    __shared__ float bl[3];
    const int tid  = threadIdx.x;
    const int row0 = blockIdx.x * 64;

    for (int flat = tid; flat < 64 * (C / 4); flat += 256) {
        int r = flat >> 5, q = flat & 31;
        int row = row0 + r;
        float4 v = make_float4(0.f, 0.f, 0.f, 0.f);
        if (row < n) v = *reinterpret_cast<const float4*>(in + (size_t)row * C + q * 4);
        hs[r][q * 4 + 0] = v.x;
        hs[r][q * 4 + 1] = v.y;
        hs[r][q * 4 + 2] = v.z;
        hs[r][q * 4 + 3] = v.w;
    }
    for (int flat = tid; flat < C * 3; flat += 256) wl[flat] = Wf3[flat];
    if (tid < 3) bl[tid] = bf3[tid];
    __syncthreads();

    if (tid < 192) {
        int r = tid / 3, j = tid % 3;
        int row = row0 + r;
        if (row < n) {
            float acc = bl[j];
#pragma unroll 4
            for (int ci = 0; ci < C; ci++) acc += hs[r][ci] * wl[ci * 3 + j];
            out[(size_t)row * 3 + j] = acc;
        }
    }
}

// ---------------------------------------------------------------------------
extern "C" void kernel_launch(void* const* d_in, const int* in_sizes, int n_in,
                              void* d_out, int out_size)
{
    const float* x_feat = (const float*)d_in[0];
    const float* W_in   = (const float*)d_in[1];
    const float* b_in   = (const float*)d_in[2];
    const float* W_res  = (const float*)d_in[3];
    const float* b_res  = (const float*)d_in[4];
    const float* W_out  = (const float*)d_in[5];
    const float* b_out  = (const float*)d_in[6];
    const float* Wf1    = (const float*)d_in[7];
    const float* bf1    = (const float*)d_in[8];
    const float* Wf2    = (const float*)d_in[9];
    const float* bf2    = (const float*)d_in[10];
    const float* Wf3    = (const float*)d_in[11];
    const float* bf3    = (const float*)d_in[12];
    const int*   nbr    = (const int*)d_in[13];
    float* out = (float*)d_out;

    const int n = in_sizes[0];   // x_feat is (N, 1)

    float *bufA, *bufB;
    cudaGetSymbolAddress((void**)&bufA, g_bufA);
    cudaGetSymbolAddress((void**)&bufB, g_bufB);

    const int gridM = (n + TM - 1) / TM;

    // h = relu(sconv(x, W_in) + b_in)
    layer_in_kernel<<<gridM, 256>>>(x_feat, bufA, W_in, b_in, nbr, n);

    // 3 residual blocks
    for (int i = 0; i < 3; i++) {
        const float* W0 = W_res + (size_t)(i * 2 + 0) * KNBR * C * C;
        const float* W1 = W_res + (size_t)(i * 2 + 1) * KNBR * C * C;
        const float* b0 = b_res + (size_t)(i * 2 + 0) * C;
        const float* b1 = b_res + (size_t)(i * 2 + 1) * C;
        sconv_kernel<<<gridM, NTHREADS>>>(bufA, bufB, W0, b0, nbr, KNBR, nullptr, 1, n);
        sconv_kernel<<<gridM, NTHREADS>>>(bufB, bufA, W1, b1, nbr, KNBR, bufA, 0, n);
    }

    // h = sconv(h, W_out) + b_out
    sconv_kernel<<<gridM, NTHREADS>>>(bufA, bufB, W_out, b_out, nbr, KNBR, nullptr, 0, n);

    // MLP: dense GEMMs via identity-gather path
    sconv_kernel<<<gridM, NTHREADS>>>(bufB, bufA, Wf1, bf1, nullptr, 1, nullptr, 1, n);
    sconv_kernel<<<gridM, NTHREADS>>>(bufA, bufB, Wf2, bf2, nullptr, 1, nullptr, 1, n);

    final_kernel<<<(n + 63) / 64, 256>>>(bufB, out, Wf3, bf3, n);
}

// round 3
// speedup vs baseline: 5.6266x; 5.6266x over previous
#include <cuda_runtime.h>
#include <cstdint>

#define C    128
#define KNBR 27
#define TM   128
#define NMAX 300000

#define N_WMAT 191                  // 162 W_res + 27 W_out + Wf1 + Wf2
#define IDXB   13824                // bytes for s_idx[27][128]
#define A_BYTES 18432               // 128 rows * 36 floats * 4
#define STAGE   35840               // A (18432) + B (32*136*4 = 17408)
#define SMEM_DYN (IDXB + 2 * STAGE) // 85504 B

__device__ float g_bufA[(size_t)NMAX * C];
__device__ float g_bufB[(size_t)NMAX * C];
__device__ float g_Wt[(size_t)N_WMAT * C * C];   // tf32-rounded, original [ci][co] layout

// ---------------------------------------------------------------------------
static __device__ __forceinline__ uint32_t smem_u32(const void* p) {
    uint32_t a;
    asm("{ .reg .u64 t; cvta.to.shared.u64 t, %1; cvt.u32.u64 %0, t; }"
        : "=r"(a) : "l"(p));
    return a;
}
static __device__ __forceinline__ void cp_async16(uint32_t dst, const void* src, bool pred) {
    int sz = pred ? 16 : 0;
    asm volatile("cp.async.cg.shared.global [%0], [%1], 16, %2;"
                 :: "r"(dst), "l"(src), "r"(sz) : "memory");
}
#define CP_COMMIT() asm volatile("cp.async.commit_group;" ::: "memory")
template <int N> static __device__ __forceinline__ void cp_wait() {
    asm volatile("cp.async.wait_group %0;" :: "n"(N) : "memory");
}
static __device__ __forceinline__ uint32_t f2tf(float x) {
    uint32_t y;
    asm("cvt.rna.tf32.f32 %0, %1;" : "=r"(y) : "f"(x));
    return y;
}
static __device__ __forceinline__ float tf32_round(float x) {
    float y;
    asm("cvt.rna.tf32.f32 %0, %1;" : "=f"(y) : "f"(x));
    return y;
}
static __device__ __forceinline__ void mma_tf32(float* c, const uint32_t* a,
                                                uint32_t b0, uint32_t b1) {
    asm volatile(
        "mma.sync.aligned.m16n8k8.row.col.f32.tf32.tf32.f32 "
        "{%0,%1,%2,%3}, {%4,%5,%6,%7}, {%8,%9}, {%0,%1,%2,%3};"
        : "+f"(c[0]), "+f"(c[1]), "+f"(c[2]), "+f"(c[3])
        : "r"(a[0]), "r"(a[1]), "r"(a[2]), "r"(a[3]), "r"(b0), "r"(b1));
}

// ---------------------------------------------------------------------------
// Weight prepass: elementwise tf32 rounding (no transpose; mma B is k-major)
// ---------------------------------------------------------------------------
__global__ void cvt_w_kernel(const float* __restrict__ W_res,
                             const float* __restrict__ W_out,
                             const float* __restrict__ Wf1,
                             const float* __restrict__ Wf2)
{
    size_t i = (size_t)blockIdx.x * 256 + threadIdx.x;
    if (i >= (size_t)N_WMAT * C * C) return;
    int mat = (int)(i >> 14);
    int off = (int)(i & 16383);
    float v;
    if (mat < 162)      v = W_res[(size_t)mat * 16384 + off];
    else if (mat < 189) v = W_out[(size_t)(mat - 162) * 16384 + off];
    else if (mat == 189) v = Wf1[off];
    else                 v = Wf2[off];
    g_Wt[i] = tf32_round(v);
}

// ---------------------------------------------------------------------------
// Gather-GEMM sconv on mma.sync tf32.
//   out[row] = ep( sum_k gather_k(in)[row] @ W[k] )
// CTA: 128 rows x 128 cols. 8 warps, warp tile 32 rows x 64 cols.
// Chunks of 32 ci; double-buffered cp.async SMEM stages.
// ---------------------------------------------------------------------------
__global__ __launch_bounds__(256, 2)
void sconv_mma(const float* __restrict__ in, float* __restrict__ out,
               const float* __restrict__ Wt, const float* __restrict__ bias,
               const float* __restrict__ resid, int relu, int Kn,
               const int* __restrict__ nbr, int n)
{
    extern __shared__ char smem[];
    const uint32_t sb = smem_u32(smem);
    const int tid = threadIdx.x, wid = tid >> 5, lane = tid & 31;
    const int lr = lane >> 2, lc = lane & 3;
    const int rg = wid & 3, cg = wid >> 2;     // warp tile: rows 32*rg, cols 64*cg
    const int row0 = blockIdx.x * TM;

    int* s_idx = (int*)smem;
    if (nbr) {
        for (int i = tid; i < Kn * TM; i += 256) {
            int r = i & 127, k = i >> 7, row = row0 + r;
            s_idx[i] = (row < n) ? nbr[(size_t)row * Kn + k] : -1;
        }
        __syncthreads();
    }

    const int total = Kn * 4;                 // 32-ci chunks

    auto produce = [&](int q) {
        const int s = q & 1;
        const int k = q >> 2, ci0 = (q & 3) * 32;
        const uint32_t stA = sb + IDXB + s * STAGE;
        const uint32_t stB = stA + A_BYTES;
        const float* Wk = Wt + (size_t)k * C * C;
#pragma unroll
        for (int i = 0; i < 4; i++) {          // A: 128 rows x 32 floats
            int u = tid + 256 * i;
            int r = u >> 3, qq = u & 7;
            int idx;
            if (nbr) idx = s_idx[(k << 7) + r];
            else     idx = (row0 + r < n) ? row0 + r : -1;
            const float* src = in + (size_t)(idx < 0 ? 0 : idx) * C + ci0 + qq * 4;
            cp_async16(stA + r * 144 + qq * 16, src, idx >= 0);
        }
#pragma unroll
        for (int i = 0; i < 4; i++) {          // B: 32 ci x 128 co
            int u = tid + 256 * i;
            int r = u >> 5, qq = u & 31;
            const float* src = Wk + (size_t)(ci0 + r) * C + qq * 4;
            cp_async16(stB + r * 544 + qq * 16, src, true);
        }
        CP_COMMIT();
    };

    float acc[2][8][4];
#pragma unroll
    for (int mt = 0; mt < 2; mt++)
#pragma unroll
        for (int nt = 0; nt < 8; nt++)
#pragma unroll
            for (int j = 0; j < 4; j++) acc[mt][nt][j] = 0.f;

    produce(0);
    if (total > 1) produce(1);

    for (int q = 0; q < total; q++) {
        const int s = q & 1;
        if (q == total - 1) cp_wait<0>();
        else                cp_wait<1>();
        __syncthreads();

        const float* As = (const float*)(smem + IDXB + s * STAGE);
        const float* Bs = (const float*)(smem + IDXB + s * STAGE + A_BYTES);

#pragma unroll
        for (int ks = 0; ks < 4; ks++) {
            uint32_t a[2][4];
#pragma unroll
            for (int mt = 0; mt < 2; mt++) {
                int r = rg * 32 + mt * 16 + lr;
                int c = ks * 8 + lc;
                a[mt][0] = f2tf(As[r * 36 + c]);
                a[mt][1] = f2tf(As[(r + 8) * 36 + c]);
                a[mt][2] = f2tf(As[r * 36 + c + 4]);
                a[mt][3] = f2tf(As[(r + 8) * 36 + c + 4]);
            }
#pragma unroll
            for (int nt = 0; nt < 8; nt++) {
                int bc = cg * 64 + nt * 8 + lr;
                int br = ks * 8 + lc;
                uint32_t b0 = __float_as_uint(Bs[br * 136 + bc]);
                uint32_t b1 = __float_as_uint(Bs[(br + 4) * 136 + bc]);
                mma_tf32(acc[0][nt], a[0], b0, b1);
                mma_tf32(acc[1][nt], a[1], b0, b1);
            }
        }
        __syncthreads();
        if (q + 2 < total) produce(q + 2);
    }

    // ---- epilogue: bias (+resid) (+relu), float2 stores from fragments ----
    float2 bv[8];
#pragma unroll
    for (int nt = 0; nt < 8; nt++)
        bv[nt] = *(const float2*)(bias + cg * 64 + nt * 8 + lc * 2);

#pragma unroll
    for (int mt = 0; mt < 2; mt++) {
        int rbase = row0 + rg * 32 + mt * 16 + lr;
#pragma unroll
        for (int half = 0; half < 2; half++) {
            int row = rbase + half * 8;
            if (row >= n) continue;
#pragma unroll
            for (int nt = 0; nt < 8; nt++) {
                int col = cg * 64 + nt * 8 + lc * 2;
                float v0 = acc[mt][nt][half * 2 + 0] + bv[nt].x;
                float v1 = acc[mt][nt][half * 2 + 1] + bv[nt].y;
                if (resid) {
                    float2 rv = *(const float2*)(resid + (size_t)row * C + col);
                    v0 += rv.x; v1 += rv.y;
                }
                if (relu) { v0 = fmaxf(v0, 0.f); v1 = fmaxf(v1, 0.f); }
                *(float2*)(out + (size_t)row * C + col) = make_float2(v0, v1);
            }
        }
    }
}

// ---------------------------------------------------------------------------
// Input layer (Cin = 1): h = relu(b + sum_k x[nbr] * Win[k])
// ---------------------------------------------------------------------------
__global__ __launch_bounds__(256)
void layer_in_kernel(const float* __restrict__ x, float* __restrict__ out,
                     const float* __restrict__ Win, const float* __restrict__ bin,
                     const int* __restrict__ nbr, int n)
{
    __shared__ float xs[TM][KNBR + 1];
    __shared__ float ws[KNBR][C];
    const int tid  = threadIdx.x;
    const int row0 = blockIdx.x * TM;

    for (int flat = tid; flat < TM * KNBR; flat += 256) {
        int r = flat / KNBR, k = flat % KNBR;
        int row = row0 + r;
        float v = 0.f;
        if (row < n) {
            int idx = nbr[(long long)row * KNBR + k];
            if (idx >= 0) v = x[idx];
        }
        xs[r][k] = v;
    }
    for (int flat = tid; flat < KNBR * C; flat += 256)
        ws[flat / C][flat % C] = Win[flat];
    __syncthreads();

    const int c  = tid & (C - 1);
    const int rg = tid >> 7;
    const float b = bin[c];
    for (int r = rg; r < TM; r += 2) {
        int row = row0 + r;
        if (row >= n) continue;
        float acc = b;
#pragma unroll
        for (int k = 0; k < KNBR; k++) acc += xs[r][k] * ws[k][c];
        out[(size_t)row * C + c] = fmaxf(acc, 0.f);
    }
}

// ---------------------------------------------------------------------------
// Final layer: out[n][0:3] = h[n] @ Wf3 + bf3
// ---------------------------------------------------------------------------
__global__ __launch_bounds__(256)
void final_kernel(const float* __restrict__ in, float* __restrict__ out,
                  const float* __restrict__ Wf3, const float* __restrict__ bf3, int n)
{
    __shared__ float hs[64][C + 1];
    __shared__ float wl[C * 3];
    __shared__ float bl[3];
    const int tid  = threadIdx.x;
    const int row0 = blockIdx.x * 64;

    for (int flat = tid; flat < 64 * (C / 4); flat += 256) {
        int r = flat >> 5, q = flat & 31;
        int row = row0 + r;
        float4 v = make_float4(0.f, 0.f, 0.f, 0.f);
        if (row < n) v = *reinterpret_cast<const float4*>(in + (size_t)row * C + q * 4);
        hs[r][q * 4 + 0] = v.x;
        hs[r][q * 4 + 1] = v.y;
        hs[r][q * 4 + 2] = v.z;
        hs[r][q * 4 + 3] = v.w;
    }
    for (int flat = tid; flat < C * 3; flat += 256) wl[flat] = Wf3[flat];
    if (tid < 3) bl[tid] = bf3[tid];
    __syncthreads();

    if (tid < 192) {
        int r = tid / 3, j = tid % 3;
        int row = row0 + r;
        if (row < n) {
            float acc = bl[j];
#pragma unroll 4
            for (int ci = 0; ci < C; ci++) acc += hs[r][ci] * wl[ci * 3 + j];
            out[(size_t)row * 3 + j] = acc;
        }
    }
}

// ---------------------------------------------------------------------------
extern "C" void kernel_launch(void* const* d_in, const int* in_sizes, int n_in,
                              void* d_out, int out_size)
{
    const float* x_feat = (const float*)d_in[0];
    const float* W_in   = (const float*)d_in[1];
    const float* b_in   = (const float*)d_in[2];
    const float* W_res  = (const float*)d_in[3];
    const float* b_res  = (const float*)d_in[4];
    const float* W_out  = (const float*)d_in[5];
    const float* b_out  = (const float*)d_in[6];
    const float* Wf1    = (const float*)d_in[7];
    const float* bf1    = (const float*)d_in[8];
    const float* Wf2    = (const float*)d_in[9];
    const float* bf2    = (const float*)d_in[10];
    const float* Wf3    = (const float*)d_in[11];
    const float* bf3    = (const float*)d_in[12];
    const int*   nbr    = (const int*)d_in[13];
    float* out = (float*)d_out;

    const int n = in_sizes[0];

    float *bufA, *bufB, *Wt;
    cudaGetSymbolAddress((void**)&bufA, g_bufA);
    cudaGetSymbolAddress((void**)&bufB, g_bufB);
    cudaGetSymbolAddress((void**)&Wt, g_Wt);

    cudaFuncSetAttribute(sconv_mma, cudaFuncAttributeMaxDynamicSharedMemorySize, SMEM_DYN);

    const int gridM = (n + TM - 1) / TM;

    const size_t wtot = (size_t)N_WMAT * C * C;
    cvt_w_kernel<<<(int)((wtot + 255) / 256), 256>>>(W_res, W_out, Wf1, Wf2);

    layer_in_kernel<<<gridM, 256>>>(x_feat, bufA, W_in, b_in, nbr, n);

    for (int i = 0; i < 3; i++) {
        const float* Wt0 = Wt + (size_t)(i * 2 + 0) * KNBR * C * C;
        const float* Wt1 = Wt + (size_t)(i * 2 + 1) * KNBR * C * C;
        const float* b0 = b_res + (size_t)(i * 2 + 0) * C;
        const float* b1 = b_res + (size_t)(i * 2 + 1) * C;
        sconv_mma<<<gridM, 256, SMEM_DYN>>>(bufA, bufB, Wt0, b0, nullptr, 1, KNBR, nbr, n);
        sconv_mma<<<gridM, 256, SMEM_DYN>>>(bufB, bufA, Wt1, b1, bufA, 0, KNBR, nbr, n);
    }

    sconv_mma<<<gridM, 256, SMEM_DYN>>>(bufA, bufB, Wt + (size_t)6 * KNBR * C * C, b_out,
                                        nullptr, 0, KNBR, nbr, n);

    sconv_mma<<<gridM, 256, SMEM_DYN>>>(bufB, bufA, Wt + (size_t)189 * C * C, bf1,
                                        nullptr, 1, 1, nullptr, n);
    sconv_mma<<<gridM, 256, SMEM_DYN>>>(bufA, bufB, Wt + (size_t)190 * C * C, bf2,
                                        nullptr, 1, 1, nullptr, n);

    final_kernel<<<(n + 63) / 64, 256>>>(bufB, out, Wf3, bf3, n);
}